// round 7
// baseline (speedup 1.0000x reference)
#include <cuda_runtime.h>
#include <cuda_fp16.h>
#include <math.h>
#include <stdint.h>

#define EPS 1e-5f
static const int HW = 112 * 112;      // 12544
static const int PPIX = 13184;        // padded pixels per image (114*114=12996 -> 13184)

#define NT    2128                    // 133 tiles/img * 16 imgs
#define TPI   133
#define STEP  152                     // persistent CTAs (GB300: 152 SMs)

// ---------------- scratch (device globals; zero-initialized) ---------------
__device__ __half g_w1r[192 * 32];                  // ±1 fp16 [co][ci]
__device__ __half g_w2r[9 * 192 * 192];             // ±1 fp16 [shift][co][ci]
__device__ __half g_w3r[32 * 192];                  // ±1 fp16 [co][ci]
__device__ __half g_h1p[(size_t)16 * PPIX * 192];   // padded NHWC fp16 (~81MB)
__device__ float  g_delta[3];
__device__ float  g_alpha[3];

// ---------------- helpers ----------------------------------------------------
__device__ __forceinline__ uint32_t smem_u32(const void* p) {
    uint32_t a;
    asm("{ .reg .u64 t; cvta.to.shared.u64 t, %1; cvt.u32.u64 %0, t; }"
        : "=r"(a) : "l"(p));
    return a;
}
#define SWZ(o) ((o) ^ (((o) >> 3) & 0x70))

#define CP_ASYNC16(saddr, gaddr) \
    asm volatile("cp.async.cg.shared.global [%0], [%1], 16;" \
        :: "r"(saddr), "l"(gaddr) : "memory")
#define CP_COMMIT() asm volatile("cp.async.commit_group;" ::: "memory")
#define CP_WAIT1()  asm volatile("cp.async.wait_group 1;" ::: "memory")
#define CP_WAIT0()  asm volatile("cp.async.wait_group 0;" ::: "memory")

__device__ __forceinline__ void ldsm4(uint32_t a, uint32_t& r0, uint32_t& r1,
                                      uint32_t& r2, uint32_t& r3) {
    asm volatile("ldmatrix.sync.aligned.m8n8.x4.shared.b16 {%0,%1,%2,%3}, [%4];"
        : "=r"(r0), "=r"(r1), "=r"(r2), "=r"(r3) : "r"(a));
}
__device__ __forceinline__ void ldsm2(uint32_t a, uint32_t& r0, uint32_t& r1) {
    asm volatile("ldmatrix.sync.aligned.m8n8.x2.shared.b16 {%0,%1}, [%2];"
        : "=r"(r0), "=r"(r1) : "r"(a));
}
__device__ __forceinline__ void mma16816(float* c, uint32_t a0, uint32_t a1,
                                         uint32_t a2, uint32_t a3,
                                         uint32_t b0, uint32_t b1) {
    asm volatile(
        "mma.sync.aligned.m16n8k16.row.col.f32.f16.f16.f32 "
        "{%0,%1,%2,%3}, {%4,%5,%6,%7}, {%8,%9}, {%0,%1,%2,%3};"
        : "+f"(c[0]), "+f"(c[1]), "+f"(c[2]), "+f"(c[3])
        : "r"(a0), "r"(a1), "r"(a2), "r"(a3), "r"(b0), "r"(b1));
}

// ---------------- TWN stats: one block per tensor (deterministic) ----------
__global__ void twn_stats_all(const float* __restrict__ w1,
                              const float* __restrict__ w2,
                              const float* __restrict__ w3) {
    __shared__ double sd[1024];
    __shared__ int    si[1024];
    __shared__ float  s_delta;
    int slot = blockIdx.x;
    const float* w = (slot == 0) ? w1 : (slot == 1) ? w2 : w3;
    int n = (slot == 1) ? 331776 : 6144;
    int tid = threadIdx.x;

    double s = 0.0;
    for (int i = tid; i < n; i += 1024) s += (double)fabsf(w[i]);
    sd[tid] = s;
    __syncthreads();
    for (int off = 512; off > 0; off >>= 1) {
        if (tid < off) sd[tid] += sd[tid + off];
        __syncthreads();
    }
    if (tid == 0) s_delta = (float)(0.7 * sd[0] / (double)n);
    __syncthreads();
    float delta = s_delta;

    double s2 = 0.0; int c = 0;
    for (int i = tid; i < n; i += 1024) {
        float a = fabsf(w[i]);
        if (a > delta) { s2 += (double)a; c++; }
    }
    sd[tid] = s2; si[tid] = c;
    __syncthreads();
    for (int off = 512; off > 0; off >>= 1) {
        if (tid < off) { sd[tid] += sd[tid + off]; si[tid] += si[tid + off]; }
        __syncthreads();
    }
    if (tid == 0) {
        g_delta[slot] = delta;
        int cnt = si[0] < 1 ? 1 : si[0];
        g_alpha[slot] = (float)(sd[0] / (double)cnt);
    }
}

// prep: blocks 0..323 -> w2 rearrange; 324 -> w1; 325 -> w3 (all ±1 fp16)
__global__ void prep_all(const float* __restrict__ w1,
                         const float* __restrict__ w2,
                         const float* __restrict__ w3) {
    int bid = blockIdx.x, tid = threadIdx.x;
    if (bid < 324) {
        float delta = g_delta[1];
        int base = bid * 1024;
#pragma unroll
        for (int it = 0; it < 4; it++) {
            int i = base + it * 256 + tid;
            int co = i / 1728; int rem = i - co * 1728;
            int ci = rem / 9;  int kk = rem - ci * 9;
            float wv = w2[i];
            float q = (fabsf(wv) > delta) ? (wv > 0.0f ? 1.0f : -1.0f) : 0.0f;
            g_w2r[((size_t)kk * 192 + co) * 192 + ci] = __float2half_rn(q);
        }
    } else if (bid == 324) {
        float delta = g_delta[0];
        for (int i = tid; i < 6144; i += 256) {
            float wv = w1[i];
            float q = (fabsf(wv) > delta) ? (wv > 0.0f ? 1.0f : -1.0f) : 0.0f;
            g_w1r[i] = __float2half_rn(q);
        }
    } else {
        float delta = g_delta[2];
        for (int i = tid; i < 6144; i += 256) {
            float wv = w3[i];
            float q = (fabsf(wv) > delta) ? (wv > 0.0f ? 1.0f : -1.0f) : 0.0f;
            g_w3r[i] = __float2half_rn(q);
        }
    }
}

// ---------------- conv1: 1x1 32->192 HMMA, BN + ReLU6 -> padded NHWC fp16 --
// grid (98, 16), 256 thr / 8 warps (2M x 4N), BM=128, BN=192, K=32.
#define C1_BN  0
#define C1_A   2048
#define C1_B   (2048 + 16384)
#define C1_SMEM (2048 + 16384 + 24576 + 1024)

__global__ __launch_bounds__(256) void conv1_mma(
    const float* __restrict__ x,
    const float* __restrict__ g1, const float* __restrict__ b1,
    const float* __restrict__ m1, const float* __restrict__ v1)
{
    extern __shared__ char dsm[];
    uint32_t sb = (smem_u32(dsm) + 1023u) & ~1023u;
    char* sbase = dsm + (sb - smem_u32(dsm));
    float* bnS = (float*)(sbase + C1_BN);

    int tid = threadIdx.x, wid = tid >> 5, lane = tid & 31;
    int img  = blockIdx.y;
    int pix0 = blockIdx.x * 128;

    // B (w1r) via cp.async: 192 rows x 64B
    for (int i = tid; i < 768; i += 256) {
        int row = i >> 2, c16 = i & 3;
        CP_ASYNC16(sb + C1_B + SWZ(row * 128 + c16 * 16),
                   (const char*)(g_w1r + row * 32) + c16 * 16);
    }
    CP_COMMIT();

    float alpha1 = g_alpha[0];
    for (int c = tid; c < 192; c += 256) {
        float is = rsqrtf(v1[c] + EPS);
        bnS[c]       = alpha1 * g1[c] * is;
        bnS[192 + c] = b1[c] - m1[c] * g1[c] * is;
    }

    // A: x fp32 NCHW -> fp16 [pix][ci] SW128
    {
        int p = tid & 127, cg = tid >> 7;
        const float* xb = x + (size_t)img * 32 * HW + pix0 + p;
#pragma unroll
        for (int i = 0; i < 8; i++) {
            int ci = cg * 16 + i * 2;
            float f0 = xb[(size_t)ci * HW];
            float f1 = xb[(size_t)(ci + 1) * HW];
            uint32_t pk = (uint32_t)__half_as_ushort(__float2half_rn(f0)) |
                          ((uint32_t)__half_as_ushort(__float2half_rn(f1)) << 16);
            *(uint32_t*)(sbase + C1_A + SWZ(p * 128 + ci * 2)) = pk;
        }
    }
    CP_WAIT0();
    __syncthreads();

    int wm = (wid >> 2) * 64;
    int wn = (wid & 3) * 48;
    float acc[4][6][4];
#pragma unroll
    for (int a = 0; a < 4; a++)
#pragma unroll
        for (int b = 0; b < 6; b++)
#pragma unroll
            for (int c = 0; c < 4; c++) acc[a][b][c] = 0.0f;

#pragma unroll
    for (int kk = 0; kk < 2; kk++) {
        uint32_t bf[6][2];
#pragma unroll
        for (int bb = 0; bb < 3; bb++) {
            int r = wn + bb * 16 + ((lane >> 4) & 1) * 8 + (lane & 7);
            int kcol = kk * 16 + ((lane >> 3) & 1) * 8;
            uint32_t q0, q1, q2, q3;
            ldsm4(sb + C1_B + SWZ(r * 128 + kcol * 2), q0, q1, q2, q3);
            bf[2 * bb][0] = q0; bf[2 * bb][1] = q1;
            bf[2 * bb + 1][0] = q2; bf[2 * bb + 1][1] = q3;
        }
#pragma unroll
        for (int mi = 0; mi < 4; mi++) {
            int m_loc = wm + mi * 16 + (lane & 7) + ((lane >> 3) & 1) * 8;
            int kh = kk * 16 + (lane >> 4) * 8;
            uint32_t a0, a1, a2, a3;
            ldsm4(sb + C1_A + SWZ(m_loc * 128 + kh * 2), a0, a1, a2, a3);
#pragma unroll
            for (int ni = 0; ni < 6; ni++)
                mma16816(acc[mi][ni], a0, a1, a2, a3, bf[ni][0], bf[ni][1]);
        }
    }

    __half* h1b = g_h1p + (size_t)img * PPIX * 192;
#pragma unroll
    for (int mi = 0; mi < 4; mi++) {
#pragma unroll
        for (int h = 0; h < 2; h++) {
            int m = wm + mi * 16 + (lane >> 2) + h * 8;
            int pu = pix0 + m;
            int y = pu / 112, xx = pu - y * 112;
            __half* dst = h1b + (size_t)((y + 1) * 114 + xx + 1) * 192;
#pragma unroll
            for (int ni = 0; ni < 6; ni++) {
                int c = wn + ni * 8 + 2 * (lane & 3);
                float y0 = fmaf(acc[mi][ni][h * 2 + 0], bnS[c],     bnS[192 + c]);
                float y1 = fmaf(acc[mi][ni][h * 2 + 1], bnS[c + 1], bnS[192 + c + 1]);
                y0 = fminf(fmaxf(y0, 0.0f), 6.0f);
                y1 = fminf(fmaxf(y1, 0.0f), 6.0f);
                uint32_t pk = (uint32_t)__half_as_ushort(__float2half_rn(y0)) |
                              ((uint32_t)__half_as_ushort(__float2half_rn(y1)) << 16);
                *(uint32_t*)(dst + c) = pk;
            }
        }
    }
}

// ---------------- conv2 (3x3) + conv3 (1x1) fused, persistent --------------
// 152 persistent CTAs, 384 thr / 12 warps. BM=96 padded pixels, BN=192,
// 2128 tiles = 152 x 14 exactly (zero wave tail). Warp tile 32x48.
// cp.async ring (3 stages) runs CONTINUOUSLY across tiles; one sync/chunk.
// h2s staging is separate from the ring so epilogue overlaps next-tile loads.
#define F_BN2  0                          // 1536
#define F_BN3  1536                       // 256
#define F_W3   2048                       // 12288
#define F_H2S  14336                      // 36864 (96 x 192 fp16)
#define F_A0   51200                      // 3 x 12288 = 36864
#define F_B0   88064                      // 3 x 24576 = 73728 (ends 161792)
#define F_SMEM (161792 + 1024)

__global__ __launch_bounds__(384, 1) void conv23_fused(
    const float* __restrict__ g2, const float* __restrict__ b2,
    const float* __restrict__ m2, const float* __restrict__ v2,
    const float* __restrict__ g3, const float* __restrict__ b3,
    const float* __restrict__ m3, const float* __restrict__ v3,
    const float* __restrict__ x, float* __restrict__ out)
{
    extern __shared__ char dsm[];
    uint32_t sb = (smem_u32(dsm) + 1023u) & ~1023u;
    char* sbase = dsm + (sb - smem_u32(dsm));
    float* bn2 = (float*)(sbase + F_BN2);
    float* bn3 = (float*)(sbase + F_BN3);

    int tid = threadIdx.x, wid = tid >> 5, lane = tid & 31;

    // ---- one-time setup: BN params + w3 tile (plain loads) ----
    float alpha2 = g_alpha[1], alpha3 = g_alpha[2];
    for (int c = tid; c < 192; c += 384) {
        float is = rsqrtf(v2[c] + EPS);
        bn2[c]       = alpha2 * g2[c] * is;
        bn2[192 + c] = b2[c] - m2[c] * g2[c] * is;
    }
    if (tid < 32) {
        float is = rsqrtf(v3[tid] + EPS);
        bn3[tid]      = alpha3 * g3[tid] * is;
        bn3[32 + tid] = b3[tid] - m3[tid] * g3[tid] * is;
    }
    for (int i = tid; i < 768; i += 384) {
        int ch = i >> 8; int rem = i & 255;
        int row = rem >> 3, c16 = rem & 7;
        uint4 v = *(const uint4*)((const char*)(g_w3r + row * 192 + ch * 64) + c16 * 16);
        *(uint4*)(sbase + F_W3 + ch * 4096 + SWZ(row * 128 + c16 * 16)) = v;
    }

    // chunk loader: chunk = sh*3 + ch, ring stage st
    auto load_chunk = [&](const __half* h1i, int pbase, int chunk, int st) {
        int sh = chunk / 3, ch = chunk - sh * 3;
        int soff = (sh / 3 - 1) * 114 + (sh % 3 - 1);
        const __half* ain = h1i + (size_t)(pbase + soff) * 192 + ch * 64;
        const __half* bw  = g_w2r + (size_t)sh * 36864 + (size_t)ch * 64;
        uint32_t sA = sb + F_A0 + st * 12288;
        uint32_t sB = sb + F_B0 + st * 24576;
#pragma unroll
        for (int p = 0; p < 2; p++) {            // A: 96 rows x 128B
            int lin = p * 384 + tid;
            int row = lin >> 3, c16 = lin & 7;
            CP_ASYNC16(sA + SWZ(row * 128 + c16 * 16),
                       (const char*)(ain + (size_t)row * 192) + c16 * 16);
        }
#pragma unroll
        for (int p = 0; p < 4; p++) {            // B: 192 rows x 128B
            int lin = p * 384 + tid;
            int row = lin >> 3, c16 = lin & 7;
            CP_ASYNC16(sB + SWZ(row * 128 + c16 * 16),
                       (const char*)(bw + (size_t)row * 192) + c16 * 16);
        }
    };

    int wm = (wid >> 2) * 32;     // 0,32,64
    int wn = (wid & 3) * 48;      // 0..144

    float acc[2][6][4];
#pragma unroll
    for (int a = 0; a < 2; a++)
#pragma unroll
        for (int b = 0; b < 6; b++)
#pragma unroll
            for (int c = 0; c < 4; c++) acc[a][b][c] = 0.0f;

    // tile bookkeeping
    int t0 = blockIdx.x;
    int pb_c = 0, pb_n = 0;
    const __half *h1c = g_h1p, *h1n = g_h1p;
    {
        int img = t0 / TPI, bx = t0 - img * TPI;
        pb_c = 115 + bx * 96; h1c = g_h1p + (size_t)img * PPIX * 192;
        int t1 = t0 + STEP;
        if (t1 < NT) {
            int im2 = t1 / TPI, bx2 = t1 - im2 * TPI;
            pb_n = 115 + bx2 * 96; h1n = g_h1p + (size_t)im2 * PPIX * 192;
        }
    }

    // prologue: 2 chunks in flight
    load_chunk(h1c, pb_c, 0, 0); CP_COMMIT();
    load_chunk(h1c, pb_c, 1, 1); CP_COMMIT();

    for (int t = t0; t < NT; t += STEP) {
        bool has_next = (t + STEP < NT);

        for (int c = 0; c < 27; c++) {
            CP_WAIT1();
            __syncthreads();
            int pc = c + 2;
            if (pc < 27)      load_chunk(h1c, pb_c, pc, pc % 3);
            else if (has_next) load_chunk(h1n, pb_n, pc - 27, (pc - 27) % 3);
            CP_COMMIT();

            int st = c % 3;
            uint32_t sA = sb + F_A0 + st * 12288;
            uint32_t sB = sb + F_B0 + st * 24576;
#pragma unroll
            for (int kk = 0; kk < 4; kk++) {
                uint32_t bf[6][2];
#pragma unroll
                for (int bb = 0; bb < 3; bb++) {
                    int r = wn + bb * 16 + ((lane >> 4) & 1) * 8 + (lane & 7);
                    int kcol = kk * 16 + ((lane >> 3) & 1) * 8;
                    uint32_t q0, q1, q2, q3;
                    ldsm4(sB + SWZ(r * 128 + kcol * 2), q0, q1, q2, q3);
                    bf[2 * bb][0] = q0; bf[2 * bb][1] = q1;
                    bf[2 * bb + 1][0] = q2; bf[2 * bb + 1][1] = q3;
                }
#pragma unroll
                for (int mi = 0; mi < 2; mi++) {
                    int m_loc = wm + mi * 16 + (lane & 7) + ((lane >> 3) & 1) * 8;
                    int kh = kk * 16 + (lane >> 4) * 8;
                    uint32_t a0, a1, a2, a3;
                    ldsm4(sA + SWZ(m_loc * 128 + kh * 2), a0, a1, a2, a3);
#pragma unroll
                    for (int ni = 0; ni < 6; ni++)
                        mma16816(acc[mi][ni], a0, a1, a2, a3, bf[ni][0], bf[ni][1]);
                }
            }
        }

        // ---- epilogue (rings untouched; next-tile loads in flight) ----
        __syncthreads();   // h2s reused across tiles: all prior reads done
        char* h2s = sbase + F_H2S;
#pragma unroll
        for (int mi = 0; mi < 2; mi++) {
#pragma unroll
            for (int h = 0; h < 2; h++) {
                int m = wm + mi * 16 + (lane >> 2) + h * 8;
#pragma unroll
                for (int ni = 0; ni < 6; ni++) {
                    int cch = wn + ni * 8 + 2 * (lane & 3);
                    float y0 = fmaf(acc[mi][ni][h * 2 + 0], bn2[cch],     bn2[192 + cch]);
                    float y1 = fmaf(acc[mi][ni][h * 2 + 1], bn2[cch + 1], bn2[192 + cch + 1]);
                    y0 = fminf(fmaxf(y0, 0.0f), 6.0f);
                    y1 = fminf(fmaxf(y1, 0.0f), 6.0f);
                    uint32_t pk = (uint32_t)__half_as_ushort(__float2half_rn(y0)) |
                                  ((uint32_t)__half_as_ushort(__float2half_rn(y1)) << 16);
                    *(uint32_t*)(h2s + (cch >> 6) * 12288 + SWZ(m * 128 + (cch & 63) * 2)) = pk;
                }
            }
        }
        __syncthreads();

        // conv3: M=96, N=32, K=192 from SMEM
        int wm3 = (wid >> 2) * 32;
        int wn3 = (wid & 3) * 8;
        float acc3[2][4];
#pragma unroll
        for (int a = 0; a < 2; a++)
#pragma unroll
            for (int c = 0; c < 4; c++) acc3[a][c] = 0.0f;

#pragma unroll
        for (int ch = 0; ch < 3; ch++) {
            uint32_t sA = sb + F_H2S + ch * 12288;
            uint32_t sB = sb + F_W3 + ch * 4096;
#pragma unroll
            for (int kk = 0; kk < 4; kk++) {
                uint32_t b0, b1;
                ldsm2(sB + SWZ((wn3 + (lane & 7)) * 128 +
                               (kk * 16 + ((lane >> 3) & 1) * 8) * 2), b0, b1);
#pragma unroll
                for (int mi = 0; mi < 2; mi++) {
                    int m_loc = wm3 + mi * 16 + (lane & 7) + ((lane >> 3) & 1) * 8;
                    int kh = kk * 16 + (lane >> 4) * 8;
                    uint32_t a0, a1, a2, a3;
                    ldsm4(sA + SWZ(m_loc * 128 + kh * 2), a0, a1, a2, a3);
                    mma16816(acc3[mi], a0, a1, a2, a3, b0, b1);
                }
            }
        }

        // BN3 + residual + masked NCHW store
        {
            size_t ioff = (size_t)(h1c - g_h1p) / ((size_t)PPIX * 192) * 32 * HW;
            const float* xi = x + ioff;
            float* oi = out + ioff;
#pragma unroll
            for (int mi = 0; mi < 2; mi++) {
#pragma unroll
                for (int h = 0; h < 2; h++) {
                    int m = wm3 + mi * 16 + (lane >> 2) + h * 8;
                    int pp = pb_c + m;
                    int yp = pp / 114, xq = pp - yp * 114;
                    if (yp >= 1 && yp <= 112 && xq >= 1 && xq <= 112) {
                        int up = (yp - 1) * 112 + (xq - 1);
                        int cc = wn3 + 2 * (lane & 3);
                        size_t i0 = (size_t)cc * HW + up;
                        size_t i1 = i0 + HW;
                        oi[i0] = fmaf(acc3[mi][h * 2 + 0], bn3[cc],     bn3[32 + cc])     + xi[i0];
                        oi[i1] = fmaf(acc3[mi][h * 2 + 1], bn3[cc + 1], bn3[32 + cc + 1]) + xi[i1];
                    }
                }
            }
        }

        // reset acc, advance tiles
#pragma unroll
        for (int a = 0; a < 2; a++)
#pragma unroll
            for (int b = 0; b < 6; b++)
#pragma unroll
                for (int c = 0; c < 4; c++) acc[a][b][c] = 0.0f;

        pb_c = pb_n; h1c = h1n;
        int t2 = t + 2 * STEP;
        if (t2 < NT) {
            int im2 = t2 / TPI, bx2 = t2 - im2 * TPI;
            pb_n = 115 + bx2 * 96; h1n = g_h1p + (size_t)im2 * PPIX * 192;
        }
    }
}

// ---------------- launch ----------------------------------------------------
extern "C" void kernel_launch(void* const* d_in, const int* in_sizes, int n_in,
                              void* d_out, int out_size) {
    const float* x  = (const float*)d_in[0];
    const float* w1 = (const float*)d_in[1];
    const float* g1 = (const float*)d_in[2];
    const float* b1 = (const float*)d_in[3];
    const float* m1 = (const float*)d_in[4];
    const float* v1 = (const float*)d_in[5];
    const float* w2 = (const float*)d_in[6];
    const float* g2 = (const float*)d_in[7];
    const float* b2 = (const float*)d_in[8];
    const float* m2 = (const float*)d_in[9];
    const float* v2 = (const float*)d_in[10];
    const float* w3 = (const float*)d_in[11];
    const float* g3 = (const float*)d_in[12];
    const float* b3 = (const float*)d_in[13];
    const float* m3 = (const float*)d_in[14];
    const float* v3 = (const float*)d_in[15];
    float* out = (float*)d_out;

    cudaFuncSetAttribute(conv1_mma, cudaFuncAttributeMaxDynamicSharedMemorySize, C1_SMEM);
    cudaFuncSetAttribute(conv23_fused, cudaFuncAttributeMaxDynamicSharedMemorySize, F_SMEM);

    twn_stats_all<<<3, 1024>>>(w1, w2, w3);
    prep_all<<<326, 256>>>(w1, w2, w3);

    conv1_mma<<<dim3(98, 16), 256, C1_SMEM>>>(x, g1, b1, m1, v1);
    conv23_fused<<<STEP, 384, F_SMEM>>>(g2, b2, m2, v2,
                                        g3, b3, m3, v3, x, out);
}

// round 8
// speedup vs baseline: 1.8511x; 1.8511x over previous
#include <cuda_runtime.h>
#include <cuda_fp16.h>
#include <math.h>
#include <stdint.h>

#define EPS 1e-5f
static const int HW = 112 * 112;      // 12544
static const int PPIX = 13184;        // padded pixels per image (114*114=12996 -> 13184)

// ---------------- scratch (device globals; zero-initialized) ---------------
__device__ __half g_w1r[192 * 32];                  // ±1 fp16 [co][ci]
__device__ __half g_w2r[9 * 192 * 192];             // ±1 fp16 [shift][co][ci]
__device__ __half g_w3r[32 * 192];                  // ±1 fp16 [co][ci]
__device__ __half g_h1p[(size_t)16 * PPIX * 192];   // padded NHWC fp16 (~81MB)
__device__ float  g_delta[3];
__device__ float  g_alpha[3];
__device__ double g_partd[3][160];
__device__ int    g_parti[3][160];

// ---------------- helpers ----------------------------------------------------
__device__ __forceinline__ uint32_t smem_u32(const void* p) {
    uint32_t a;
    asm("{ .reg .u64 t; cvta.to.shared.u64 t, %1; cvt.u32.u64 %0, t; }"
        : "=r"(a) : "l"(p));
    return a;
}
#define SWZ(o) ((o) ^ (((o) >> 3) & 0x70))

#define CP_ASYNC16(saddr, gaddr) \
    asm volatile("cp.async.cg.shared.global [%0], [%1], 16;" \
        :: "r"(saddr), "l"(gaddr) : "memory")
#define CP_COMMIT() asm volatile("cp.async.commit_group;" ::: "memory")
#define CP_WAIT1()  asm volatile("cp.async.wait_group 1;" ::: "memory")
#define CP_WAIT0()  asm volatile("cp.async.wait_group 0;" ::: "memory")

__device__ __forceinline__ void ldsm4(uint32_t a, uint32_t& r0, uint32_t& r1,
                                      uint32_t& r2, uint32_t& r3) {
    asm volatile("ldmatrix.sync.aligned.m8n8.x4.shared.b16 {%0,%1,%2,%3}, [%4];"
        : "=r"(r0), "=r"(r1), "=r"(r2), "=r"(r3) : "r"(a));
}
__device__ __forceinline__ void ldsm2(uint32_t a, uint32_t& r0, uint32_t& r1) {
    asm volatile("ldmatrix.sync.aligned.m8n8.x2.shared.b16 {%0,%1}, [%2];"
        : "=r"(r0), "=r"(r1) : "r"(a));
}
__device__ __forceinline__ void mma16816(float* c, uint32_t a0, uint32_t a1,
                                         uint32_t a2, uint32_t a3,
                                         uint32_t b0, uint32_t b1) {
    asm volatile(
        "mma.sync.aligned.m16n8k16.row.col.f32.f16.f16.f32 "
        "{%0,%1,%2,%3}, {%4,%5,%6,%7}, {%8,%9}, {%0,%1,%2,%3};"
        : "+f"(c[0]), "+f"(c[1]), "+f"(c[2]), "+f"(c[3])
        : "r"(a0), "r"(a1), "r"(a2), "r"(a3), "r"(b0), "r"(b1));
}

// ---------------- TWN stats: batched 2-stage deterministic reduction -------
__global__ void stats_abs_all(const float* __restrict__ w1,
                              const float* __restrict__ w2,
                              const float* __restrict__ w3) {
    __shared__ double sd[256];
    int slot = blockIdx.y;
    const float* w = (slot == 0) ? w1 : (slot == 1) ? w2 : w3;
    int n = (slot == 1) ? 331776 : 6144;
    int tid = threadIdx.x;
    int g = blockIdx.x * 256 + tid, stride = gridDim.x * 256;
    double s = 0.0;
    for (int i = g; i < n; i += stride) s += (double)fabsf(w[i]);
    sd[tid] = s; __syncthreads();
    for (int o = 128; o > 0; o >>= 1) {
        if (tid < o) sd[tid] += sd[tid + o];
        __syncthreads();
    }
    if (tid == 0) g_partd[slot][blockIdx.x] = sd[0];
}
__global__ void stats_delta_all() {
    __shared__ double sd[256];
    int slot = blockIdx.x;
    int n = (slot == 1) ? 331776 : 6144;
    int tid = threadIdx.x;
    sd[tid] = (tid < 148) ? g_partd[slot][tid] : 0.0; __syncthreads();
    for (int o = 128; o > 0; o >>= 1) {
        if (tid < o) sd[tid] += sd[tid + o];
        __syncthreads();
    }
    if (tid == 0) g_delta[slot] = (float)(0.7 * sd[0] / (double)n);
}
__global__ void stats_alpha_all(const float* __restrict__ w1,
                                const float* __restrict__ w2,
                                const float* __restrict__ w3) {
    __shared__ double sd[256];
    __shared__ int    si[256];
    int slot = blockIdx.y;
    const float* w = (slot == 0) ? w1 : (slot == 1) ? w2 : w3;
    int n = (slot == 1) ? 331776 : 6144;
    int tid = threadIdx.x;
    int g = blockIdx.x * 256 + tid, stride = gridDim.x * 256;
    float delta = g_delta[slot];
    double s = 0.0; int c = 0;
    for (int i = g; i < n; i += stride) {
        float a = fabsf(w[i]);
        if (a > delta) { s += (double)a; c++; }
    }
    sd[tid] = s; si[tid] = c; __syncthreads();
    for (int o = 128; o > 0; o >>= 1) {
        if (tid < o) { sd[tid] += sd[tid + o]; si[tid] += si[tid + o]; }
        __syncthreads();
    }
    if (tid == 0) { g_partd[slot][blockIdx.x] = sd[0]; g_parti[slot][blockIdx.x] = si[0]; }
}
__global__ void stats_alpha_fin_all() {
    __shared__ double sd[256];
    __shared__ int    si[256];
    int slot = blockIdx.x;
    int tid = threadIdx.x;
    sd[tid] = (tid < 148) ? g_partd[slot][tid] : 0.0;
    si[tid] = (tid < 148) ? g_parti[slot][tid] : 0;
    __syncthreads();
    for (int o = 128; o > 0; o >>= 1) {
        if (tid < o) { sd[tid] += sd[tid + o]; si[tid] += si[tid + o]; }
        __syncthreads();
    }
    if (tid == 0) {
        int cnt = si[0] < 1 ? 1 : si[0];
        g_alpha[slot] = (float)(sd[0] / (double)cnt);
    }
}

// prep: blocks 0..323 -> w2 rearrange; 324 -> w1; 325 -> w3 (all ±1 fp16)
__global__ void prep_all(const float* __restrict__ w1,
                         const float* __restrict__ w2,
                         const float* __restrict__ w3) {
    int bid = blockIdx.x, tid = threadIdx.x;
    if (bid < 324) {
        float delta = g_delta[1];
        int base = bid * 1024;
#pragma unroll
        for (int it = 0; it < 4; it++) {
            int i = base + it * 256 + tid;
            int co = i / 1728; int rem = i - co * 1728;
            int ci = rem / 9;  int kk = rem - ci * 9;
            float wv = w2[i];
            float q = (fabsf(wv) > delta) ? (wv > 0.0f ? 1.0f : -1.0f) : 0.0f;
            g_w2r[((size_t)kk * 192 + co) * 192 + ci] = __float2half_rn(q);
        }
    } else if (bid == 324) {
        float delta = g_delta[0];
        for (int i = tid; i < 6144; i += 256) {
            float wv = w1[i];
            float q = (fabsf(wv) > delta) ? (wv > 0.0f ? 1.0f : -1.0f) : 0.0f;
            g_w1r[i] = __float2half_rn(q);
        }
    } else {
        float delta = g_delta[2];
        for (int i = tid; i < 6144; i += 256) {
            float wv = w3[i];
            float q = (fabsf(wv) > delta) ? (wv > 0.0f ? 1.0f : -1.0f) : 0.0f;
            g_w3r[i] = __float2half_rn(q);
        }
    }
}

// ---------------- conv1: 1x1 32->192 HMMA, BN + ReLU6 -> padded NHWC fp16 --
// grid (98, 16), 256 thr / 8 warps (2M x 4N), BM=128, BN=192, K=32.
#define C1_BN  0
#define C1_A   2048
#define C1_B   (2048 + 16384)
#define C1_SMEM (2048 + 16384 + 24576 + 1024)

__global__ __launch_bounds__(256) void conv1_mma(
    const float* __restrict__ x,
    const float* __restrict__ g1, const float* __restrict__ b1,
    const float* __restrict__ m1, const float* __restrict__ v1)
{
    extern __shared__ char dsm[];
    uint32_t sb = (smem_u32(dsm) + 1023u) & ~1023u;
    char* sbase = dsm + (sb - smem_u32(dsm));
    float* bnS = (float*)(sbase + C1_BN);

    int tid = threadIdx.x, wid = tid >> 5, lane = tid & 31;
    int img  = blockIdx.y;
    int pix0 = blockIdx.x * 128;

    for (int i = tid; i < 768; i += 256) {
        int row = i >> 2, c16 = i & 3;
        CP_ASYNC16(sb + C1_B + SWZ(row * 128 + c16 * 16),
                   (const char*)(g_w1r + row * 32) + c16 * 16);
    }
    CP_COMMIT();

    float alpha1 = g_alpha[0];
    for (int c = tid; c < 192; c += 256) {
        float is = rsqrtf(v1[c] + EPS);
        bnS[c]       = alpha1 * g1[c] * is;
        bnS[192 + c] = b1[c] - m1[c] * g1[c] * is;
    }

    {
        int p = tid & 127, cg = tid >> 7;
        const float* xb = x + (size_t)img * 32 * HW + pix0 + p;
#pragma unroll
        for (int i = 0; i < 8; i++) {
            int ci = cg * 16 + i * 2;
            float f0 = xb[(size_t)ci * HW];
            float f1 = xb[(size_t)(ci + 1) * HW];
            uint32_t pk = (uint32_t)__half_as_ushort(__float2half_rn(f0)) |
                          ((uint32_t)__half_as_ushort(__float2half_rn(f1)) << 16);
            *(uint32_t*)(sbase + C1_A + SWZ(p * 128 + ci * 2)) = pk;
        }
    }
    CP_WAIT0();
    __syncthreads();

    int wm = (wid >> 2) * 64;
    int wn = (wid & 3) * 48;
    float acc[4][6][4];
#pragma unroll
    for (int a = 0; a < 4; a++)
#pragma unroll
        for (int b = 0; b < 6; b++)
#pragma unroll
            for (int c = 0; c < 4; c++) acc[a][b][c] = 0.0f;

#pragma unroll
    for (int kk = 0; kk < 2; kk++) {
        uint32_t bf[6][2];
#pragma unroll
        for (int bb = 0; bb < 3; bb++) {
            int r = wn + bb * 16 + ((lane >> 4) & 1) * 8 + (lane & 7);
            int kcol = kk * 16 + ((lane >> 3) & 1) * 8;
            uint32_t q0, q1, q2, q3;
            ldsm4(sb + C1_B + SWZ(r * 128 + kcol * 2), q0, q1, q2, q3);
            bf[2 * bb][0] = q0; bf[2 * bb][1] = q1;
            bf[2 * bb + 1][0] = q2; bf[2 * bb + 1][1] = q3;
        }
#pragma unroll
        for (int mi = 0; mi < 4; mi++) {
            int m_loc = wm + mi * 16 + (lane & 7) + ((lane >> 3) & 1) * 8;
            int kh = kk * 16 + (lane >> 4) * 8;
            uint32_t a0, a1, a2, a3;
            ldsm4(sb + C1_A + SWZ(m_loc * 128 + kh * 2), a0, a1, a2, a3);
#pragma unroll
            for (int ni = 0; ni < 6; ni++)
                mma16816(acc[mi][ni], a0, a1, a2, a3, bf[ni][0], bf[ni][1]);
        }
    }

    __half* h1b = g_h1p + (size_t)img * PPIX * 192;
#pragma unroll
    for (int mi = 0; mi < 4; mi++) {
#pragma unroll
        for (int h = 0; h < 2; h++) {
            int m = wm + mi * 16 + (lane >> 2) + h * 8;
            int pu = pix0 + m;
            int y = pu / 112, xx = pu - y * 112;
            __half* dst = h1b + (size_t)((y + 1) * 114 + xx + 1) * 192;
#pragma unroll
            for (int ni = 0; ni < 6; ni++) {
                int c = wn + ni * 8 + 2 * (lane & 3);
                float y0 = fmaf(acc[mi][ni][h * 2 + 0], bnS[c],     bnS[192 + c]);
                float y1 = fmaf(acc[mi][ni][h * 2 + 1], bnS[c + 1], bnS[192 + c + 1]);
                y0 = fminf(fmaxf(y0, 0.0f), 6.0f);
                y1 = fminf(fmaxf(y1, 0.0f), 6.0f);
                uint32_t pk = (uint32_t)__half_as_ushort(__float2half_rn(y0)) |
                              ((uint32_t)__half_as_ushort(__float2half_rn(y1)) << 16);
                *(uint32_t*)(dst + c) = pk;
            }
        }
    }
}

// ---------------- conv2 (3x3) + conv3 (1x1) fused, 3-stage + reg pipeline ---
// grid (67, 16), 384 thr / 12 warps. BM=192, BN=192, warp tile 64x48.
// 3-stage cp.async ring, one sync per chunk; register fragment double-buffer
// across kk so ldmatrix latency hides under the 24 MMAs of the previous kk.
#define F_BN2  0                          // 1536
#define F_BN3  1536                       // 256
#define F_W3   2048                       // 12288
#define F_A0   14336                      // 3 x 24576 = 73728
#define F_B0   (14336 + 73728)            // 3 x 24576 = 73728  (ends 161792)
#define F_H2S  14336                      // 73728, overlays A ring after mainloop
#define F_SMEM (161792 + 1024)

__global__ __launch_bounds__(384, 1) void conv23_fused(
    const float* __restrict__ g2, const float* __restrict__ b2,
    const float* __restrict__ m2, const float* __restrict__ v2,
    const float* __restrict__ g3, const float* __restrict__ b3,
    const float* __restrict__ m3, const float* __restrict__ v3,
    const float* __restrict__ x, float* __restrict__ out)
{
    extern __shared__ char dsm[];
    uint32_t sb = (smem_u32(dsm) + 1023u) & ~1023u;
    char* sbase = dsm + (sb - smem_u32(dsm));
    float* bn2 = (float*)(sbase + F_BN2);
    float* bn3 = (float*)(sbase + F_BN3);

    int tid = threadIdx.x, wid = tid >> 5, lane = tid & 31;
    int img   = blockIdx.y;
    int pbase = 115 + blockIdx.x * 192;

    for (int i = tid; i < 768; i += 384) {
        int ch = i >> 8; int rem = i & 255;
        int row = rem >> 3, c16 = rem & 7;
        CP_ASYNC16(sb + F_W3 + ch * 4096 + SWZ(row * 128 + c16 * 16),
                   (const char*)(g_w3r + row * 192 + ch * 64) + c16 * 16);
    }

    float alpha2 = g_alpha[1], alpha3 = g_alpha[2];
    for (int c = tid; c < 192; c += 384) {
        float is = rsqrtf(v2[c] + EPS);
        bn2[c]       = alpha2 * g2[c] * is;
        bn2[192 + c] = b2[c] - m2[c] * g2[c] * is;
    }
    if (tid < 32) {
        float is = rsqrtf(v3[tid] + EPS);
        bn3[tid]      = alpha3 * g3[tid] * is;
        bn3[32 + tid] = b3[tid] - m3[tid] * g3[tid] * is;
    }

    const __half* h1i = g_h1p + (size_t)img * PPIX * 192;

    auto load_chunk = [&](int chunk) {
        int sh = chunk / 3, ch = chunk - sh * 3;
        int soff = (sh / 3 - 1) * 114 + (sh % 3 - 1);
        const __half* ain = h1i + (size_t)(pbase + soff) * 192 + ch * 64;
        const __half* bw  = g_w2r + (size_t)sh * 36864 + (size_t)ch * 64;
        int st = chunk % 3;
        uint32_t sA = sb + F_A0 + st * 24576;
        uint32_t sB = sb + F_B0 + st * 24576;
#pragma unroll
        for (int p = 0; p < 4; p++) {
            int lin = p * 384 + tid;
            int row = lin >> 3, c16 = lin & 7;
            CP_ASYNC16(sA + SWZ(row * 128 + c16 * 16),
                       (const char*)(ain + (size_t)row * 192) + c16 * 16);
        }
#pragma unroll
        for (int p = 0; p < 4; p++) {
            int lin = p * 384 + tid;
            int row = lin >> 3, c16 = lin & 7;
            CP_ASYNC16(sB + SWZ(row * 128 + c16 * 16),
                       (const char*)(bw + (size_t)row * 192) + c16 * 16);
        }
    };

    int wm = (wid >> 2) * 64;     // 0,64,128
    int wn = (wid & 3) * 48;      // 0..144

    // precomputed intra-warp ldsm lane addressing
    int bR    = wn + ((lane >> 4) & 1) * 8 + (lane & 7);   // B row base (+bb*16)
    int bKsel = ((lane >> 3) & 1) * 8;                     // B k column sub-offset
    int aM    = wm + (lane & 7) + ((lane >> 3) & 1) * 8;   // A row base (+mi*16)
    int aKsel = (lane >> 4) * 8;                           // A k column sub-offset

    float acc[4][6][4];
#pragma unroll
    for (int a = 0; a < 4; a++)
#pragma unroll
        for (int b = 0; b < 6; b++)
#pragma unroll
            for (int c = 0; c < 4; c++) acc[a][b][c] = 0.0f;

    uint32_t bf[2][6][2], af[2][4][4];

    load_chunk(0); CP_COMMIT();
    load_chunk(1); CP_COMMIT();

    for (int c = 0; c < 27; c++) {
        if (c == 26) { CP_WAIT0(); } else { CP_WAIT1(); }
        __syncthreads();
        if (c + 2 < 27) { load_chunk(c + 2); CP_COMMIT(); }

        int st = c % 3;
        uint32_t sA = sb + F_A0 + st * 24576;
        uint32_t sB = sb + F_B0 + st * 24576;

        // prefetch fragments for kk=0
#pragma unroll
        for (int bb = 0; bb < 3; bb++) {
            uint32_t q0, q1, q2, q3;
            ldsm4(sB + SWZ((bR + bb * 16) * 128 + bKsel * 2), q0, q1, q2, q3);
            bf[0][2 * bb][0] = q0; bf[0][2 * bb][1] = q1;
            bf[0][2 * bb + 1][0] = q2; bf[0][2 * bb + 1][1] = q3;
        }
#pragma unroll
        for (int mi = 0; mi < 4; mi++)
            ldsm4(sA + SWZ((aM + mi * 16) * 128 + aKsel * 2),
                  af[0][mi][0], af[0][mi][1], af[0][mi][2], af[0][mi][3]);

#pragma unroll
        for (int kk = 0; kk < 4; kk++) {
            int cur = kk & 1, nxt = cur ^ 1;
            if (kk < 3) {
                int kb = (kk + 1) * 16;
#pragma unroll
                for (int bb = 0; bb < 3; bb++) {
                    uint32_t q0, q1, q2, q3;
                    ldsm4(sB + SWZ((bR + bb * 16) * 128 + (kb + bKsel) * 2),
                          q0, q1, q2, q3);
                    bf[nxt][2 * bb][0] = q0; bf[nxt][2 * bb][1] = q1;
                    bf[nxt][2 * bb + 1][0] = q2; bf[nxt][2 * bb + 1][1] = q3;
                }
#pragma unroll
                for (int mi = 0; mi < 4; mi++)
                    ldsm4(sA + SWZ((aM + mi * 16) * 128 + (kb + aKsel) * 2),
                          af[nxt][mi][0], af[nxt][mi][1],
                          af[nxt][mi][2], af[nxt][mi][3]);
            }
#pragma unroll
            for (int mi = 0; mi < 4; mi++)
#pragma unroll
                for (int ni = 0; ni < 6; ni++)
                    mma16816(acc[mi][ni], af[cur][mi][0], af[cur][mi][1],
                             af[cur][mi][2], af[cur][mi][3],
                             bf[cur][ni][0], bf[cur][ni][1]);
        }
    }
    __syncthreads();   // ring reads done before h2s overlay

    // ---- BN2 + ReLU6 -> SMEM h2 tile (fp16, 3 SW128 chunks of 64 ci) ----
    char* h2s = sbase + F_H2S;
#pragma unroll
    for (int mi = 0; mi < 4; mi++) {
#pragma unroll
        for (int h = 0; h < 2; h++) {
            int m = wm + mi * 16 + (lane >> 2) + h * 8;
#pragma unroll
            for (int ni = 0; ni < 6; ni++) {
                int cch = wn + ni * 8 + 2 * (lane & 3);
                float y0 = fmaf(acc[mi][ni][h * 2 + 0], bn2[cch],     bn2[192 + cch]);
                float y1 = fmaf(acc[mi][ni][h * 2 + 1], bn2[cch + 1], bn2[192 + cch + 1]);
                y0 = fminf(fmaxf(y0, 0.0f), 6.0f);
                y1 = fminf(fmaxf(y1, 0.0f), 6.0f);
                uint32_t pk = (uint32_t)__half_as_ushort(__float2half_rn(y0)) |
                              ((uint32_t)__half_as_ushort(__float2half_rn(y1)) << 16);
                *(uint32_t*)(h2s + (cch >> 6) * 24576 + SWZ(m * 128 + (cch & 63) * 2)) = pk;
            }
        }
    }
    __syncthreads();

    // ---- conv3: M=192, N=32, K=192 from SMEM ----
    int wm3 = (wid >> 2) * 64;
    int wn3 = (wid & 3) * 8;
    float acc3[4][4];
#pragma unroll
    for (int a = 0; a < 4; a++)
#pragma unroll
        for (int c = 0; c < 4; c++) acc3[a][c] = 0.0f;

#pragma unroll
    for (int ch = 0; ch < 3; ch++) {
        uint32_t sA = sb + F_H2S + ch * 24576;
        uint32_t sB = sb + F_W3 + ch * 4096;
#pragma unroll
        for (int kk = 0; kk < 4; kk++) {
            uint32_t b0, b1;
            ldsm2(sB + SWZ((wn3 + (lane & 7)) * 128 +
                           (kk * 16 + ((lane >> 3) & 1) * 8) * 2), b0, b1);
#pragma unroll
            for (int mi = 0; mi < 4; mi++) {
                int m_loc = wm3 + mi * 16 + (lane & 7) + ((lane >> 3) & 1) * 8;
                int kh = kk * 16 + (lane >> 4) * 8;
                uint32_t a0, a1, a2, a3;
                ldsm4(sA + SWZ(m_loc * 128 + kh * 2), a0, a1, a2, a3);
                mma16816(acc3[mi], a0, a1, a2, a3, b0, b1);
            }
        }
    }

    // ---- BN3 + residual + masked NCHW store ----
    const float* xi = x + (size_t)img * 32 * HW;
    float* oi = out + (size_t)img * 32 * HW;
#pragma unroll
    for (int mi = 0; mi < 4; mi++) {
#pragma unroll
        for (int h = 0; h < 2; h++) {
            int m = wm3 + mi * 16 + (lane >> 2) + h * 8;
            int pp = pbase + m;
            int yp = pp / 114, xq = pp - yp * 114;
            if (yp >= 1 && yp <= 112 && xq >= 1 && xq <= 112) {
                int up = (yp - 1) * 112 + (xq - 1);
                int c = wn3 + 2 * (lane & 3);
                size_t i0 = (size_t)c * HW + up;
                size_t i1 = i0 + HW;
                oi[i0] = fmaf(acc3[mi][h * 2 + 0], bn3[c],     bn3[32 + c])     + xi[i0];
                oi[i1] = fmaf(acc3[mi][h * 2 + 1], bn3[c + 1], bn3[32 + c + 1]) + xi[i1];
            }
        }
    }
}

// ---------------- launch ----------------------------------------------------
extern "C" void kernel_launch(void* const* d_in, const int* in_sizes, int n_in,
                              void* d_out, int out_size) {
    const float* x  = (const float*)d_in[0];
    const float* w1 = (const float*)d_in[1];
    const float* g1 = (const float*)d_in[2];
    const float* b1 = (const float*)d_in[3];
    const float* m1 = (const float*)d_in[4];
    const float* v1 = (const float*)d_in[5];
    const float* w2 = (const float*)d_in[6];
    const float* g2 = (const float*)d_in[7];
    const float* b2 = (const float*)d_in[8];
    const float* m2 = (const float*)d_in[9];
    const float* v2 = (const float*)d_in[10];
    const float* w3 = (const float*)d_in[11];
    const float* g3 = (const float*)d_in[12];
    const float* b3 = (const float*)d_in[13];
    const float* m3 = (const float*)d_in[14];
    const float* v3 = (const float*)d_in[15];
    float* out = (float*)d_out;

    cudaFuncSetAttribute(conv1_mma, cudaFuncAttributeMaxDynamicSharedMemorySize, C1_SMEM);
    cudaFuncSetAttribute(conv23_fused, cudaFuncAttributeMaxDynamicSharedMemorySize, F_SMEM);

    stats_abs_all<<<dim3(148, 3), 256>>>(w1, w2, w3);
    stats_delta_all<<<3, 256>>>();
    stats_alpha_all<<<dim3(148, 3), 256>>>(w1, w2, w3);
    stats_alpha_fin_all<<<3, 256>>>();
    prep_all<<<326, 256>>>(w1, w2, w3);

    conv1_mma<<<dim3(98, 16), 256, C1_SMEM>>>(x, g1, b1, m1, v1);
    conv23_fused<<<dim3(67, 16), 384, F_SMEM>>>(g2, b2, m2, v2,
                                                g3, b3, m3, v3, x, out);
}